// round 3
// baseline (speedup 1.0000x reference)
#include <cuda_runtime.h>
#include <cuda_bf16.h>

// QuantumLayer analytic collapse:
//   out[b,i] = prod_{c : c <= i, (i-c) % L == 0} cos(x[b,c])
// Derivation: RZ layers are unit-modulus diagonal phases -> cancel in |.|^2;
// CNOT chains are GF(2)-linear basis permutations; Z_i after L layers pulls
// back to a parity of initial-wire Z's (binomial parity / Kummer ->
// membership (i-c) & (L-1) == 0 <=> (i-c) % L == 0 for power-of-2 L);
// product measure factorizes the expectation into a product of cos(x_c).
// q_weights is mathematically irrelevant to the output.
//
// Equivalent recurrence per row:  p[j] = cos(x[j]);  p[j] *= p[j-L] for j>=L.

constexpr int N = 10;          // wires (q_weights.shape[1])
constexpr int ROWS = 128;      // rows per block; ROWS*N = 1280 floats = 320 float4

template<int L>
__global__ __launch_bounds__(ROWS)
void quantum_rows_kernel(const float* __restrict__ x,
                         float* __restrict__ out, int B) {
    __shared__ float s[ROWS * N];
    const int base  = blockIdx.x * ROWS;
    const int nrows = min(ROWS, B - base);
    const int nelem = nrows * N;

    // ---- Coalesced vectorized stage-in ----
    const float* gx = x + base * N;
    if (nelem == ROWS * N) {
        const float4* gx4 = (const float4*)gx;
        float4* s4 = (float4*)s;
        #pragma unroll
        for (int k = threadIdx.x; k < ROWS * N / 4; k += ROWS)
            s4[k] = gx4[k];
    } else {
        for (int k = threadIdx.x; k < nelem; k += ROWS)
            s[k] = gx[k];
    }
    __syncthreads();

    // ---- Per-row compute, all in registers ----
    if (threadIdx.x < nrows) {
        float p[N];
        float* r = s + threadIdx.x * N;
        #pragma unroll
        for (int j = 0; j < N; j++) p[j] = __cosf(r[j]);
        #pragma unroll
        for (int j = L; j < N; j++) p[j] *= p[j - L];
        #pragma unroll
        for (int j = 0; j < N; j++) r[j] = p[j];
    }
    __syncthreads();

    // ---- Coalesced vectorized stage-out ----
    float* go = out + base * N;
    if (nelem == ROWS * N) {
        const float4* s4 = (const float4*)s;
        float4* go4 = (float4*)go;
        #pragma unroll
        for (int k = threadIdx.x; k < ROWS * N / 4; k += ROWS)
            go4[k] = s4[k];
    } else {
        for (int k = threadIdx.x; k < nelem; k += ROWS)
            go[k] = s[k];
    }
}

// Generic fallback (any L), one thread per output element.
__global__ void quantum_elem_kernel(const float* __restrict__ x,
                                    float* __restrict__ out,
                                    int total, int L) {
    int t = blockIdx.x * blockDim.x + threadIdx.x;
    if (t >= total) return;
    int b = t / N;
    int i = t - b * N;
    const float* row = x + b * N;
    float p = 1.0f;
    for (int c = i; c >= 0; c -= L)
        p *= cosf(row[c]);
    out[t] = p;
}

extern "C" void kernel_launch(void* const* d_in, const int* in_sizes, int n_in,
                              void* d_out, int out_size) {
    const float* x = (const float*)d_in[0];
    // d_in[1] = q_weights: unused (phases cancel in probabilities)
    const int L = in_sizes[1] / N;        // layers
    const int B = out_size / N;           // batch

    float* out = (float*)d_out;
    int blocks = (B + ROWS - 1) / ROWS;

    switch (L) {
        case 1: quantum_rows_kernel<1><<<blocks, ROWS>>>(x, out, B); break;
        case 2: quantum_rows_kernel<2><<<blocks, ROWS>>>(x, out, B); break;
        case 4: quantum_rows_kernel<4><<<blocks, ROWS>>>(x, out, B); break;
        case 8: quantum_rows_kernel<8><<<blocks, ROWS>>>(x, out, B); break;
        default: {
            int total = out_size;
            quantum_elem_kernel<<<(total + 255) / 256, 256>>>(x, out, total, L);
        }
    }
}

// round 5
// speedup vs baseline: 1.3961x; 1.3961x over previous
#include <cuda_runtime.h>
#include <cuda_bf16.h>

// QuantumLayer analytic collapse:
//   out[b,i] = prod_{c <= i, ((i-c) & (L-1)) == 0} cos(x[b,c])
// Derivation: RZ layers are unit-modulus diagonal phases -> cancel in |.|^2;
// the CNOT chain is the GF(2) prefix-sum matrix M; Z_i after L layers pulls
// back to the parity set = row i of M^L, (M^L)_{ic} = C(i-c+L-1, L-1) mod 2,
// odd iff ((i-c) & (L-1)) == 0 (Kummer). The initial state is a product
// measure, so the parity expectation factorizes into prod cos(x_c).
// q_weights is mathematically irrelevant to the output.

constexpr int N = 10;   // wires (q_weights.shape[1])

// Specialized: power-of-2 L -> membership is stride-L. One thread per output
// element; <=ceil(N/L) independent predicated loads + MUFU cos, no sync.
template<int L>
__global__ __launch_bounds__(256)
void quantum_elem_kernel(const float* __restrict__ x,
                         float* __restrict__ out, int total) {
    int t = blockIdx.x * blockDim.x + threadIdx.x;
    if (t >= total) return;
    int b = t / N;            // constexpr divisor -> mul/shift, no IDIV
    int i = t - b * N;
    const float* row = x + b * N;

    float p = __cosf(__ldg(row + i));
    #pragma unroll
    for (int k = 1; k * L < N; k++) {
        int c = i - k * L;
        if (c >= 0) p *= __cosf(__ldg(row + c));
    }
    out[t] = p;
}

// Generic fallback: any L, Kummer mask rule.
__global__ __launch_bounds__(256)
void quantum_generic_kernel(const float* __restrict__ x,
                            float* __restrict__ out,
                            int total, int Lm1) {
    int t = blockIdx.x * blockDim.x + threadIdx.x;
    if (t >= total) return;
    int b = t / N;
    int i = t - b * N;
    const float* row = x + b * N;
    float p = 1.0f;
    #pragma unroll
    for (int c = i; c >= 0; --c)
        if (((i - c) & Lm1) == 0)
            p *= __cosf(__ldg(row + c));
    out[t] = p;
}

extern "C" void kernel_launch(void* const* d_in, const int* in_sizes, int n_in,
                              void* d_out, int out_size) {
    const float* x = (const float*)d_in[0];
    // d_in[1] = q_weights: unused (phases cancel in probabilities)
    const int L = in_sizes[1] / N;   // layers
    const int total = out_size;      // B * N
    float* out = (float*)d_out;

    const int threads = 256;
    const int blocks = (total + threads - 1) / threads;

    switch (L) {
        case 1: quantum_elem_kernel<1><<<blocks, threads>>>(x, out, total); break;
        case 2: quantum_elem_kernel<2><<<blocks, threads>>>(x, out, total); break;
        case 4: quantum_elem_kernel<4><<<blocks, threads>>>(x, out, total); break;
        case 8: quantum_elem_kernel<8><<<blocks, threads>>>(x, out, total); break;
        default:
            quantum_generic_kernel<<<blocks, threads>>>(x, out, total, L - 1);
    }
}